// round 7
// baseline (speedup 1.0000x reference)
#include <cuda_runtime.h>
#include <cuda_fp16.h>
#include <cstdint>

#define NPTS 1000000
#define WRES 64
#define NSAMP (NPTS * 12)

// Transposed grids in fp16, layout [3, H, W, 16] per scale, concatenated.
__device__ __align__(16) __half g_trans[5898240];

// Per-j (j = sIdx*3 + ci) lookup: {plane_off (halfs), 0.5f*(H-1) bits, H-1, ci}
__constant__ uint4 c_tab[12] = {
    {      0, 0x427E0000u,  127u, 0u},
    { 131072, 0x427E0000u,  127u, 1u},
    { 262144, 0x427E0000u,  127u, 2u},
    { 393216, 0x42FF0000u,  255u, 0u},
    { 655360, 0x42FF0000u,  255u, 1u},
    { 917504, 0x42FF0000u,  255u, 2u},
    {1179648, 0x437F8000u,  511u, 0u},
    {1703936, 0x437F8000u,  511u, 1u},
    {2228224, 0x437F8000u,  511u, 2u},
    {2752512, 0x43FFC000u, 1023u, 0u},
    {3801088, 0x43FFC000u, 1023u, 1u},
    {4849664, 0x43FFC000u, 1023u, 2u},
};

// -------- fused transpose+convert: [3,16,H,64] fp32 -> [3,H,64,16] fp16 --------
__global__ void __launch_bounds__(256) transpose_all(const float* __restrict__ g0,
                                                     const float* __restrict__ g1,
                                                     const float* __restrict__ g2,
                                                     const float* __restrict__ g3) {
    int idx = blockIdx.x * blockDim.x + threadIdx.x;
    if (idx >= 368640) return;   // 3*64*(128+256+512+1024)
    const float* g;
    int H, toff, local, hshift;
    if (idx < 24576)       { g = g0; H = 128;  toff = 0;       local = idx;          hshift = 7;  }
    else if (idx < 73728)  { g = g1; H = 256;  toff = 393216;  local = idx - 24576;  hshift = 8;  }
    else if (idx < 172032) { g = g2; H = 512;  toff = 1179648; local = idx - 73728;  hshift = 9;  }
    else                   { g = g3; H = 1024; toff = 2752512; local = idx - 172032; hshift = 10; }

    int w = local & 63;
    int rest = local >> 6;            // ci*H + h
    int h = rest & (H - 1);
    int ci = rest >> hshift;
    const float* src = g + ((size_t)(ci * 16) * H + h) * WRES + w;
    float tmp[16];
    size_t fstride = (size_t)H * WRES;
#pragma unroll
    for (int f = 0; f < 16; f++) tmp[f] = src[f * fstride];

    __half2 hv[8];
#pragma unroll
    for (int f = 0; f < 8; f++) hv[f] = __floats2half2_rn(tmp[2 * f], tmp[2 * f + 1]);

    uint4* dst = reinterpret_cast<uint4*>(g_trans + toff + (size_t)local * 16);
    uint4 a, b;
    a.x = *(uint32_t*)&hv[0]; a.y = *(uint32_t*)&hv[1];
    a.z = *(uint32_t*)&hv[2]; a.w = *(uint32_t*)&hv[3];
    b.x = *(uint32_t*)&hv[4]; b.y = *(uint32_t*)&hv[5];
    b.z = *(uint32_t*)&hv[6]; b.w = *(uint32_t*)&hv[7];
    dst[0] = a;
    dst[1] = b;
}

// -------- main sample kernel: 4 lanes per sample, half2 math --------
// lane r in group: bit0 = feature half (16B chunk), bit1 = x-corner.
__global__ void __launch_bounds__(256) sample_k(const float* __restrict__ pts,
                                                const float* __restrict__ radius,
                                                float* __restrict__ out) {
    int t = blockIdx.x * blockDim.x + threadIdx.x;
    int g = t >> 2;               // sample id = n*12 + j
    int r = t & 3;
    int n = g / 12;
    int j = g - n * 12;

    uint4 tab = c_tab[j];
    int   plane_off = (int)tab.x;
    float fys = __uint_as_float(tab.y);   // 0.5f*(H-1)
    int   Hm1 = (int)tab.z;
    int   ci  = (int)tab.w;

    float xv = __ldg(pts + n * 3 + ci);
    float yv = __ldg(radius + n);

    float fx = (xv + 1.0f) * 31.5f;       // 0.5*(W-1) = 31.5
    float fy = (yv + 1.0f) * fys;
    float x0f = floorf(fx);
    float y0f = floorf(fy);
    float wx = fx - x0f;
    float wy = fy - y0f;
    int x0 = min(max((int)x0f, 0), 63);
    int x1 = min(x0 + 1, 63);
    int y0 = min(max((int)y0f, 0), Hm1);
    int y1 = min(y0 + 1, Hm1);

    int xs = (r & 2) ? x1 : x0;
    int hsel = (r & 1) * 8;               // feature-half offset (halfs)

    const __half* tb = g_trans + plane_off;
    const uint4* pA = reinterpret_cast<const uint4*>(tb + (size_t)((y0 << 6) + xs) * 16 + hsel);
    const uint4* pB = reinterpret_cast<const uint4*>(tb + (size_t)((y1 << 6) + xs) * 16 + hsel);
    uint4 vA = *pA;
    uint4 vB = *pB;

    float wxr = (r & 2) ? wx : (1.0f - wx);
    __half2 w0h = __float2half2_rn((1.0f - wy) * wxr);
    __half2 w1h = __float2half2_rn(wy * wxr);

    const __half2* hA = reinterpret_cast<const __half2*>(&vA);
    const __half2* hB = reinterpret_cast<const __half2*>(&vB);
    __half2 acc[4];
#pragma unroll
    for (int k = 0; k < 4; k++)
        acc[k] = __hfma2(hA[k], w0h, __hmul2(hB[k], w1h));

    // combine the two x-corners (lane bit1) — packed half2 shuffle
#pragma unroll
    for (int k = 0; k < 4; k++) {
        uint32_t u = *reinterpret_cast<uint32_t*>(&acc[k]);
        uint32_t o = __shfl_xor_sync(0xffffffffu, u, 2);
        acc[k] = __hadd2(acc[k], *reinterpret_cast<__half2*>(&o));
    }

    // store one 16B quarter per lane: chunk = (r&1)*2 + (r>>1)
    __half2 s0 = (r & 2) ? acc[2] : acc[0];
    __half2 s1 = (r & 2) ? acc[3] : acc[1];
    float2 lo = __half22float2(s0);
    float2 hi = __half22float2(s1);
    int chunk = ((r & 1) << 1) | (r >> 1);
    float4* o = reinterpret_cast<float4*>(out + (size_t)n * 192 + j * 16 + chunk * 4);
    *o = make_float4(lo.x, lo.y, hi.x, hi.y);
}

extern "C" void kernel_launch(void* const* d_in, const int* in_sizes, int n_in,
                              void* d_out, int out_size) {
    const float* pts    = (const float*)d_in[0];
    const float* radius = (const float*)d_in[1];
    float* out = (float*)d_out;

    transpose_all<<<(368640 + 255) / 256, 256>>>((const float*)d_in[2],
                                                 (const float*)d_in[3],
                                                 (const float*)d_in[4],
                                                 (const float*)d_in[5]);

    // NSAMP*4 = 48,000,000 threads; 256/block -> 187500 blocks exactly
    sample_k<<<187500, 256>>>(pts, radius, out);
}